// round 1
// baseline (speedup 1.0000x reference)
#include <cuda_runtime.h>
#include <cuda_bf16.h>
#include <cstdint>

// Output = one_hot(arange(N), N) @ W = I @ W = W.
// So this reduces to an 8 MiB device-to-device copy of W (16384 x 128 fp32).
// Pure HBM-bound: 16 MiB total traffic -> ~2 us floor on GB300 HBM3e.

__global__ void __launch_bounds__(256) copy_w_kernel(const float4* __restrict__ src,
                                                     float4* __restrict__ dst,
                                                     int n_vec4) {
    int stride = gridDim.x * blockDim.x;
    for (int i = blockIdx.x * blockDim.x + threadIdx.x; i < n_vec4; i += stride) {
        dst[i] = src[i];
    }
}

extern "C" void kernel_launch(void* const* d_in, const int* in_sizes, int n_in,
                              void* d_out, int out_size) {
    const float4* W = (const float4*)d_in[0];
    float4* out = (float4*)d_out;
    // out_size elements of fp32; total bytes = out_size*4, vec4 count = out_size/4.
    int n_vec4 = out_size / 4;  // 16384*128/4 = 524288

    // One full wave: 148 SMs, a few CTAs each; grid-stride handles remainder.
    int threads = 256;
    int blocks = (n_vec4 + threads - 1) / threads;  // 2048 CTAs
    if (blocks > 148 * 8) blocks = 148 * 8;
    copy_w_kernel<<<blocks, threads>>>(W, out, n_vec4);
}